// round 16
// baseline (speedup 1.0000x reference)
#include <cuda_runtime.h>
#include <cuda_bf16.h>
#include <math.h>
#include <stdint.h>

#define TE 64
#define THREADS 512
#define ESTR 68   // EMBT row stride: conflict-free distributed reads

// ---- smem layout (32-bit word offsets) ----
#define OFF_W0    0        // packed W0 units [64 n][4 tq-swz][16B]       1024
#define OFF_B2    1024     // packed units [64 n][4 k][4 tq][16B]         4096
#define OFF_B3    5120     // packed units [112 n][4 k][4 tq][16B]        7168
// union region: A-frags + EMBT alias MIXS
#define OFF_AHI   12288    // A hi frag units [4 ms][4 k][8 g][4 tq]      2048
#define OFF_ALO   14336    // A lo                                        2048
#define OFF_EMBT  16384    // fp32 [8][68]                                544
#define OFF_MIXS  12288    // fp32 [64][116] gates (aliases above)        7424
#define OFF_US    19712    // [64][4]                                     256
#define OFF_SVS   19968    // [64][84]                                    5376
#define OFF_DOTS  25344    // [64][20] (stride 20: conflict-free)         1280
#define MIX_STRIDE 116
#define SMEM_FLOATS 26624
#define SMEM_BYTES (SMEM_FLOATS * 4)   // 106496 B -> 2 CTAs/SM

__device__ __forceinline__ float swishf(float x) {
    return x * (1.0f / (1.0f + __expf(-x)));
}

__device__ __forceinline__ void split2(float x0, float x1, uint32_t& h, uint32_t& l) {
    __nv_bfloat162 hb = __floats2bfloat162_rn(x0, x1);
    float r0 = x0 - __bfloat162float(hb.x);
    float r1 = x1 - __bfloat162float(hb.y);
    __nv_bfloat162 lb = __floats2bfloat162_rn(r0, r1);
    h = *(uint32_t*)&hb;
    l = *(uint32_t*)&lb;
}

__device__ __forceinline__ void mma_bf16(float* d, uint32_t a0, uint32_t a1,
                                         uint32_t a2, uint32_t a3,
                                         uint32_t b0, uint32_t b1) {
    asm volatile(
        "mma.sync.aligned.m16n8k16.row.col.f32.bf16.bf16.f32 "
        "{%0,%1,%2,%3}, {%4,%5,%6,%7}, {%8,%9}, {%0,%1,%2,%3};"
        : "+f"(d[0]), "+f"(d[1]), "+f"(d[2]), "+f"(d[3])
        : "r"(a0), "r"(a1), "r"(a2), "r"(a3), "r"(b0), "r"(b1));
}

__device__ __forceinline__ void red4(float* addr, float x, float y, float z, float w) {
    asm volatile("red.global.add.v4.f32 [%0], {%1,%2,%3,%4};"
                 :: "l"(addr), "f"(x), "f"(y), "f"(z), "f"(w) : "memory");
}

extern "C" __global__ void __launch_bounds__(THREADS, 2)
mp_kernel(const float* __restrict__ vectors,
          const float* __restrict__ node_s,
          const float* __restrict__ node_v,
          const float* __restrict__ W0,
          const float* __restrict__ W1,
          const float* __restrict__ W2,
          const int* __restrict__ senders,
          const int* __restrict__ receivers,
          float* __restrict__ out,
          int E, int numTiles)
{
    extern __shared__ float sm[];
    uint32_t* smw = (uint32_t*)sm;
    const int t = threadIdx.x;

    // ---- one-time weight staging (packed 16B units, swizzled) ----
    for (int i = t; i < 256; i += THREADS) {          // W0 units: k16-padded (half zero)
        int n = i >> 2, q = i & 3;
        float x0 = W0[(2*q)   * 64 + n] * 0.35355339059327373f;
        float x1 = W0[(2*q+1) * 64 + n] * 0.35355339059327373f;
        uint32_t hw, lw;
        split2(x0, x1, hw, lw);
        int base = OFF_W0 + (n * 4 + ((q + n) & 3)) * 4;
        smw[base + 0] = hw; smw[base + 1] = 0u;
        smw[base + 2] = lw; smw[base + 3] = 0u;
    }
    for (int i = t; i < 64 * 32; i += THREADS) {      // B2[n][k] = W1[k][n]/8
        int n = i >> 5, wd = i & 31;
        int k = wd >> 3, r = wd & 7, tq = r & 3, half = r >> 2;
        float x0 = W1[(2*wd)   * 64 + n] * 0.125f;
        float x1 = W1[(2*wd+1) * 64 + n] * 0.125f;
        uint32_t hw, lw;
        split2(x0, x1, hw, lw);
        int kk = (k + n) & 3;
        int base = OFF_B2 + (n * 16 + kk * 4 + tq) * 4;
        smw[base + half] = hw;
        smw[base + 2 + half] = lw;
    }
    for (int i = t; i < 112 * 32; i += THREADS) {     // B3[n][k] = W2[k][n]*scl(n)
        int n = i >> 5, wd = i & 31;
        int k = wd >> 3, r = wd & 7, tq = r & 3, half = r >> 2;
        float scl = (n >= 96) ? 0.03125f * 1.224744871391589f : 0.03125f;
        float x0 = W2[(2*wd)   * 112 + n] * scl;
        float x1 = W2[(2*wd+1) * 112 + n] * scl;
        uint32_t hw, lw;
        split2(x0, x1, hw, lw);
        int kk = (k + n) & 3;
        int base = OFF_B3 + (n * 16 + kk * 4 + tq) * 4;
        smw[base + half] = hw;
        smw[base + 2 + half] = lw;
    }
    __syncthreads();

    const int w = t >> 5, lane = t & 31;
    const int g = lane >> 2, tq = lane & 3;
    const int ms = w >> 2, nq = w & 3;           // 4 M-strips x 4 N-quarters
    const int mb = ms * 16;
    const int aunit0 = (ms * 128 + g * 4 + tq) * 4;   // + k*128 words

    // thread-constant base pointers
    const uint32_t* abh = smw + OFF_AHI + aunit0;
    const uint32_t* abl = smw + OFF_ALO + aunit0;
    const int nb2 = nq * 16;
    const int r2 = (nb2 + g) & 3;
    const uint32_t* bb2 = smw + OFF_B2 + (nb2 + g) * 64 + tq * 4;   // + n*512 + kk*16
    const int nb3 = (nq < 2) ? 32 * nq : 64 + 24 * (nq - 2);
    const int nt3 = (nq < 2) ? 4 : 3;
    const int r3 = (nb3 + g) & 3;
    const uint32_t* bb3 = smw + OFF_B3 + (nb3 + g) * 64 + tq * 4;   // + n*512 + kk*16
    // GEMM1: emb reads (rows mb+g, mb+g+8; k = 2tq, 2tq+1) and W0 units
    const float* embp = sm + OFF_EMBT + 136 * tq + mb + g;
    const uint32_t* w0u0;
    const uint32_t* w0u1;
    {
        int row0 = nb2 + g;
        int row1 = nb2 + 8 + g;
        w0u0 = smw + OFF_W0 + (row0 * 4 + ((tq + row0) & 3)) * 4;
        w0u1 = smw + OFF_W0 + (row1 * 4 + ((tq + row1) & 3)) * 4;
    }

    // per-edge identity (8 threads/edge)
    const int ge = t >> 3, gsub = t & 7;
    float* gdst = sm + OFF_SVS + ge * 84;

    for (int tile = blockIdx.x; tile < numTiles; tile += gridDim.x) {
        const int e0 = tile * TE;
        const int geg = e0 + ge;
        const bool gok = (geg < E);

        // prefetch receiver index for stage G
        int rec = gok ? receivers[geg] : 0;

        // ---- stage A: geometry + radial embedding (warps 0-1) ----
        if (t < TE) {
            int e = e0 + t;
            float vx = 0.f, vy = 0.f, vz = 0.f;
            if (e < E) { vx = vectors[3*e+0]; vy = vectors[3*e+1]; vz = vectors[3*e+2]; }
            float r = sqrtf(vx*vx + vy*vy + vz*vz);
            float rinv = (r > 1e-12f) ? 1.0f / r : 0.0f;
            sm[OFF_US + 4*t+0] = vx*rinv; sm[OFF_US + 4*t+1] = vy*rinv;
            sm[OFF_US + 4*t+2] = vz*rinv; sm[OFF_US + 4*t+3] = 0.f;
            float env = 0.0f;
            if (r < 1.0f) {
                float x2 = r*r, x4 = x2*x2, x6 = x4*x2, x7 = x6*r, x8 = x4*x4;
                env = 1.0f - 28.0f*x6 + 48.0f*x7 - 21.0f*x8;
            }
            float pref = (r > 0.0f) ? 1.4142135623730951f * rinv * env : 0.0f;
            float s1, c1;
            sincosf(3.14159265358979323846f * r, &s1, &c1);
            float sn = s1, sp = 0.0f, c2 = 2.0f * c1;
            #pragma unroll
            for (int n = 0; n < 8; n++) {
                sm[OFF_EMBT + n*ESTR + t] = pref * sn;
                float nx = c2 * sn - sp; sp = sn; sn = nx;
            }
        }
        // gather issue (latency hidden behind stage B), 8 threads/edge
        int snd = gok ? senders[geg] : 0;
        const float4* sp4 = (const float4*)(node_s + (size_t)snd * 32);
        const float4* vp4 = (const float4*)(node_v + (size_t)snd * 48);
        float4 gr[3];
        #pragma unroll
        for (int q = 0; q < 3; q++) {
            int f4i = gsub + 8*q;                 // 0..23, valid < 20
            float4 val = {0.f, 0.f, 0.f, 0.f};
            if (gok && f4i < 20) val = (f4i < 8) ? sp4[f4i] : vp4[f4i - 8];
            gr[q] = val;
        }
        __syncthreads();

        // ---- stage B: GEMM1 via bf16 mma (K=8 padded to 16), -> A unit k=nq ----
        {
            float e00 = embp[0], e01 = embp[ESTR];
            float e10 = embp[8], e11 = embp[ESTR + 8];
            uint32_t a0h, a0l, a1h, a1l;
            split2(e00, e01, a0h, a0l);
            split2(e10, e11, a1h, a1l);
            float acc1[2][4];
            #pragma unroll
            for (int n = 0; n < 2; n++)
                #pragma unroll
                for (int j = 0; j < 4; j++) acc1[n][j] = 0.f;
            uint4 b0 = *(const uint4*)w0u0;     // [bh0, 0, bl0, 0]
            uint4 b1 = *(const uint4*)w0u1;
            mma_bf16(acc1[0], a0h, a1h, 0u, 0u, b0.x, b0.y);
            mma_bf16(acc1[1], a0h, a1h, 0u, 0u, b1.x, b1.y);
            mma_bf16(acc1[0], a0h, a1h, 0u, 0u, b0.z, b0.w);
            mma_bf16(acc1[1], a0h, a1h, 0u, 0u, b1.z, b1.w);
            mma_bf16(acc1[0], a0l, a1l, 0u, 0u, b0.x, b0.y);
            mma_bf16(acc1[1], a0l, a1l, 0u, 0u, b1.x, b1.y);

            uint32_t h0,l0,h1,l1,h2,l2,h3,l3;
            split2(swishf(acc1[0][0]), swishf(acc1[0][1]), h0, l0);
            split2(swishf(acc1[0][2]), swishf(acc1[0][3]), h1, l1);
            split2(swishf(acc1[1][0]), swishf(acc1[1][1]), h2, l2);
            split2(swishf(acc1[1][2]), swishf(acc1[1][3]), h3, l3);
            *(uint4*)(abh + nq * 128) = make_uint4(h0, h1, h2, h3);
            *(uint4*)(abl + nq * 128) = make_uint4(l0, l1, l2, l3);
        }
        // land gather into smem; compute dots (2 per thread)
        {
            #pragma unroll
            for (int q = 0; q < 3; q++) {
                int f4i = gsub + 8*q;
                if (f4i < 20) *(float4*)(gdst + 4 * f4i) = gr[q];
            }
            __syncwarp();
            const float* usf = sm + OFF_US + 4 * ge;
            float ux = usf[0], uy = usf[1], uz = usf[2];
            #pragma unroll
            for (int q = 0; q < 2; q++) {
                int c = 2 * gsub + q;
                const float* vv = gdst + 32 + 3 * c;
                sm[OFF_DOTS + ge * 20 + c] = ux*vv[0] + uy*vv[1] + uz*vv[2];
            }
        }
        __syncthreads();

        // ---- stage C: GEMM2 via bf16 mma (3-pass split, pass-interleaved) ----
        float acc2[2][4];
        {
            #pragma unroll
            for (int n = 0; n < 2; n++)
                #pragma unroll
                for (int j = 0; j < 4; j++) acc2[n][j] = 0.f;
            #pragma unroll
            for (int k = 0; k < 4; k++) {
                const int kk = (k + r2) & 3;
                uint4 ah = *(const uint4*)(abh + k * 128);
                uint4 al = *(const uint4*)(abl + k * 128);
                uint4 b0 = *(const uint4*)(bb2 + kk * 16);
                uint4 b1 = *(const uint4*)(bb2 + 512 + kk * 16);
                mma_bf16(acc2[0], ah.x, ah.y, ah.z, ah.w, b0.x, b0.y);
                mma_bf16(acc2[1], ah.x, ah.y, ah.z, ah.w, b1.x, b1.y);
                mma_bf16(acc2[0], ah.x, ah.y, ah.z, ah.w, b0.z, b0.w);
                mma_bf16(acc2[1], ah.x, ah.y, ah.z, ah.w, b1.z, b1.w);
                mma_bf16(acc2[0], al.x, al.y, al.z, al.w, b0.x, b0.y);
                mma_bf16(acc2[1], al.x, al.y, al.z, al.w, b1.x, b1.y);
            }
        }
        __syncthreads();   // all h1 reads done before overwrite

        // ---- stage D: swish(h2), split -> packed A fragment unit k=nq ----
        {
            uint32_t h0,l0,h1,l1,h2,l2,h3,l3;
            split2(swishf(acc2[0][0]), swishf(acc2[0][1]), h0, l0);
            split2(swishf(acc2[0][2]), swishf(acc2[0][3]), h1, l1);
            split2(swishf(acc2[1][0]), swishf(acc2[1][1]), h2, l2);
            split2(swishf(acc2[1][2]), swishf(acc2[1][3]), h3, l3);
            *(uint4*)(abh + nq * 128) = make_uint4(h0, h1, h2, h3);
            *(uint4*)(abl + nq * 128) = make_uint4(l0, l1, l2, l3);
        }
        __syncthreads();

        // ---- stage E: GEMM3 via bf16 mma (3-pass split, pass-interleaved) ----
        {
            float acc3[4][4];
            #pragma unroll
            for (int n = 0; n < 4; n++)
                #pragma unroll
                for (int j = 0; j < 4; j++) acc3[n][j] = 0.f;
            #pragma unroll
            for (int k = 0; k < 4; k++) {
                const int kk = (k + r3) & 3;
                uint4 ah = *(const uint4*)(abh + k * 128);
                uint4 al = *(const uint4*)(abl + k * 128);
                uint4 b[4];
                #pragma unroll
                for (int n = 0; n < 4; n++)
                    if (n < nt3) b[n] = *(const uint4*)(bb3 + n * 512 + kk * 16);
                #pragma unroll
                for (int n = 0; n < 4; n++)
                    if (n < nt3) mma_bf16(acc3[n], ah.x, ah.y, ah.z, ah.w, b[n].x, b[n].y);
                #pragma unroll
                for (int n = 0; n < 4; n++)
                    if (n < nt3) mma_bf16(acc3[n], ah.x, ah.y, ah.z, ah.w, b[n].z, b[n].w);
                #pragma unroll
                for (int n = 0; n < 4; n++)
                    if (n < nt3) mma_bf16(acc3[n], al.x, al.y, al.z, al.w, b[n].x, b[n].y);
            }
            __syncthreads();   // A/EMBT fully read before gate store aliases them
            #pragma unroll
            for (int n = 0; n < 4; n++) {
                if (n < nt3) {
                    int col = nb3 + n*8 + 2*tq;
                    *(float2*)(sm + OFF_MIXS + (mb + g) * MIX_STRIDE + col) =
                        make_float2(acc3[n][0], acc3[n][1]);
                    *(float2*)(sm + OFF_MIXS + (mb + g + 8) * MIX_STRIDE + col) =
                        make_float2(acc3[n][2], acc3[n][3]);
                }
            }
        }
        __syncthreads();

        // ---- stage G: static channel-aligned message formation + scatter ----
        {
            const bool ok = gok;
            const float* dst = gdst;
            const float* dts = sm + OFF_DOTS + ge * 20;
            const float* mx  = sm + OFF_MIXS + ge * MIX_STRIDE;
            float* obase = out + (size_t)rec * 240;
            const float* usf = sm + OFF_US + 4 * ge;
            float u3[3];
            u3[0] = usf[0]; u3[1] = usf[1]; u3[2] = usf[2];

            // msg_s: v4 #gsub (s * gate); threads 0-3 also v4 #8+gsub (dot * gate)
            {
                float4 s4 = *(const float4*)(dst + 4 * gsub);
                float4 m4 = *(const float4*)(mx + 4 * gsub);
                if (ok) red4(obase + 4 * gsub,
                             s4.x*m4.x, s4.y*m4.y, s4.z*m4.z, s4.w*m4.w);
            }
            if (gsub < 4) {
                float4 d4 = *(const float4*)(dts + 4 * gsub);
                float4 m4 = *(const float4*)(mx + 32 + 4 * gsub);
                if (ok) red4(obase + 32 + 4 * gsub,
                             d4.x*m4.x, d4.y*m4.y, d4.z*m4.z, d4.w*m4.w);
            }

            // msg_v: this thread owns channels [8*gsub, 8*gsub+8) = 24 floats
            float gj[8];
            *(float4*)(gj)     = *(const float4*)(mx + 48 + 8 * gsub);
            *(float4*)(gj + 4) = *(const float4*)(mx + 52 + 8 * gsub);
            float* vb = obase + 48 + 24 * gsub;

            if (gsub < 2) {               // filtered v: x = v[c][i]
                #pragma unroll
                for (int q4 = 0; q4 < 6; q4++) {
                    float4 vv = *(const float4*)(dst + 32 + 24 * gsub + 4 * q4);
                    float vq[4] = {vv.x, vv.y, vv.z, vv.w};
                    float val[4];
                    #pragma unroll
                    for (int q = 0; q < 4; q++) {
                        const int f = 4 * q4 + q;
                        val[q] = vq[q] * gj[f / 3];
                    }
                    if (ok) red4(vb + 4 * q4, val[0], val[1], val[2], val[3]);
                }
            } else if (gsub < 6) {        // s x Y1: x = s[c-16] * u[i]
                float sreg[8];
                *(float4*)(sreg)     = *(const float4*)(dst + 8 * gsub - 16);
                *(float4*)(sreg + 4) = *(const float4*)(dst + 8 * gsub - 12);
                #pragma unroll
                for (int q4 = 0; q4 < 6; q4++) {
                    float val[4];
                    #pragma unroll
                    for (int q = 0; q < 4; q++) {
                        const int f = 4 * q4 + q;
                        val[q] = sreg[f / 3] * u3[f % 3] * gj[f / 3];
                    }
                    if (ok) red4(vb + 4 * q4, val[0], val[1], val[2], val[3]);
                }
            } else {                      // v x Y2: x = u[i]*dot[c2] - v[c2][i]/3
                float dreg[8];
                *(float4*)(dreg)     = *(const float4*)(dts + 8 * gsub - 48);
                *(float4*)(dreg + 4) = *(const float4*)(dts + 8 * gsub - 44);
                #pragma unroll
                for (int q4 = 0; q4 < 6; q4++) {
                    float4 vv = *(const float4*)(dst + 32 + 24 * gsub - 144 + 4 * q4);
                    float vq[4] = {vv.x, vv.y, vv.z, vv.w};
                    float val[4];
                    #pragma unroll
                    for (int q = 0; q < 4; q++) {
                        const int f = 4 * q4 + q;
                        val[q] = (u3[f % 3] * dreg[f / 3]
                                  - vq[q] * 0.3333333333333333f) * gj[f / 3];
                    }
                    if (ok) red4(vb + 4 * q4, val[0], val[1], val[2], val[3]);
                }
            }
        }
        __syncthreads();   // smem reused next tile
    }
}

extern "C" void kernel_launch(void* const* d_in, const int* in_sizes, int n_in,
                              void* d_out, int out_size) {
    const float* vectors   = (const float*)d_in[0];
    const float* node_s    = (const float*)d_in[1];
    const float* node_v    = (const float*)d_in[2];
    const float* W0        = (const float*)d_in[3];
    const float* W1        = (const float*)d_in[4];
    const float* W2        = (const float*)d_in[5];
    const int*   senders   = (const int*)d_in[6];
    const int*   receivers = (const int*)d_in[7];
    float*       out       = (float*)d_out;

    int E = in_sizes[6];
    int numTiles = (E + TE - 1) / TE;

    cudaFuncSetAttribute(mp_kernel, cudaFuncAttributeMaxDynamicSharedMemorySize, SMEM_BYTES);

    cudaMemsetAsync(d_out, 0, (size_t)out_size * sizeof(float), 0);

    int grid = 296;                      // persistent: 2 CTAs/SM, 32 warps/SM
    if (grid > numTiles) grid = numTiles;
    mp_kernel<<<grid, THREADS, SMEM_BYTES>>>(vectors, node_s, node_v, W0, W1, W2,
                                             senders, receivers, out, E, numTiles);
}

// round 17
// speedup vs baseline: 1.6579x; 1.6579x over previous
#include <cuda_runtime.h>
#include <cuda_bf16.h>
#include <math.h>
#include <stdint.h>

#define TE 64
#define THREADS 512
#define ESTR 68   // EMBT row stride: conflict-free distributed reads

// ---- smem layout (32-bit word offsets) ----
#define OFF_W0    0        // packed W0 units [64 n][4 tq-swz][16B]       1024
#define OFF_B2    1024     // packed units [64 n][4 k][4 tq][16B]         4096
#define OFF_B3    5120     // packed units [112 n][4 k][4 tq][16B]        7168
// union region: A-frags + EMBT alias MIXS
#define OFF_AHI   12288    // A hi frag units [4 ms][4 k][8 g][4 tq]      2048
#define OFF_ALO   14336    // A lo                                        2048
#define OFF_EMBT  16384    // fp32 [8][68]                                544
#define OFF_MIXS  12288    // fp32 [64][116] gates (aliases above)        7424
#define OFF_US    19712    // [64][4]                                     256
#define OFF_SVS   19968    // [64][84]                                    5376
#define OFF_DOTS  25344    // [64][20] (stride 20: conflict-free)         1280
#define MIX_STRIDE 116
#define SMEM_FLOATS 26624
#define SMEM_BYTES (SMEM_FLOATS * 4)   // 106496 B -> 2 CTAs/SM

__device__ __forceinline__ float swishf(float x) {
    return x * (1.0f / (1.0f + __expf(-x)));
}

__device__ __forceinline__ void split2(float x0, float x1, uint32_t& h, uint32_t& l) {
    __nv_bfloat162 hb = __floats2bfloat162_rn(x0, x1);
    float r0 = x0 - __bfloat162float(hb.x);
    float r1 = x1 - __bfloat162float(hb.y);
    __nv_bfloat162 lb = __floats2bfloat162_rn(r0, r1);
    h = *(uint32_t*)&hb;
    l = *(uint32_t*)&lb;
}

__device__ __forceinline__ void mma_bf16(float* d, uint32_t a0, uint32_t a1,
                                         uint32_t a2, uint32_t a3,
                                         uint32_t b0, uint32_t b1) {
    asm volatile(
        "mma.sync.aligned.m16n8k16.row.col.f32.bf16.bf16.f32 "
        "{%0,%1,%2,%3}, {%4,%5,%6,%7}, {%8,%9}, {%0,%1,%2,%3};"
        : "+f"(d[0]), "+f"(d[1]), "+f"(d[2]), "+f"(d[3])
        : "r"(a0), "r"(a1), "r"(a2), "r"(a3), "r"(b0), "r"(b1));
}

extern "C" __global__ void __launch_bounds__(THREADS, 2)
mp_kernel(const float* __restrict__ vectors,
          const float* __restrict__ node_s,
          const float* __restrict__ node_v,
          const float* __restrict__ W0,
          const float* __restrict__ W1,
          const float* __restrict__ W2,
          const int* __restrict__ senders,
          const int* __restrict__ receivers,
          float* __restrict__ out,
          int E, int numTiles)
{
    extern __shared__ float sm[];
    uint32_t* smw = (uint32_t*)sm;
    const int t = threadIdx.x;

    // ---- one-time weight staging (packed 16B units, swizzled) ----
    for (int i = t; i < 256; i += THREADS) {          // W0 units: k16-padded (half zero)
        int n = i >> 2, q = i & 3;
        float x0 = W0[(2*q)   * 64 + n] * 0.35355339059327373f;
        float x1 = W0[(2*q+1) * 64 + n] * 0.35355339059327373f;
        uint32_t hw, lw;
        split2(x0, x1, hw, lw);
        int base = OFF_W0 + (n * 4 + ((q + n) & 3)) * 4;
        smw[base + 0] = hw; smw[base + 1] = 0u;
        smw[base + 2] = lw; smw[base + 3] = 0u;
    }
    for (int i = t; i < 64 * 32; i += THREADS) {      // B2[n][k] = W1[k][n]/8
        int n = i >> 5, wd = i & 31;
        int k = wd >> 3, r = wd & 7, tq = r & 3, half = r >> 2;
        float x0 = W1[(2*wd)   * 64 + n] * 0.125f;
        float x1 = W1[(2*wd+1) * 64 + n] * 0.125f;
        uint32_t hw, lw;
        split2(x0, x1, hw, lw);
        int kk = (k + n) & 3;
        int base = OFF_B2 + (n * 16 + kk * 4 + tq) * 4;
        smw[base + half] = hw;
        smw[base + 2 + half] = lw;
    }
    for (int i = t; i < 112 * 32; i += THREADS) {     // B3[n][k] = W2[k][n]*scl(n)
        int n = i >> 5, wd = i & 31;
        int k = wd >> 3, r = wd & 7, tq = r & 3, half = r >> 2;
        float scl = (n >= 96) ? 0.03125f * 1.224744871391589f : 0.03125f;
        float x0 = W2[(2*wd)   * 112 + n] * scl;
        float x1 = W2[(2*wd+1) * 112 + n] * scl;
        uint32_t hw, lw;
        split2(x0, x1, hw, lw);
        int kk = (k + n) & 3;
        int base = OFF_B3 + (n * 16 + kk * 4 + tq) * 4;
        smw[base + half] = hw;
        smw[base + 2 + half] = lw;
    }
    __syncthreads();

    const int w = t >> 5, lane = t & 31;
    const int g = lane >> 2, tq = lane & 3;
    const int ms = w >> 2, nq = w & 3;           // 4 M-strips x 4 N-quarters
    const int mb = ms * 16;
    const int aunit0 = (ms * 128 + g * 4 + tq) * 4;   // + k*128 words

    // thread-constant base pointers
    const uint32_t* abh = smw + OFF_AHI + aunit0;
    const uint32_t* abl = smw + OFF_ALO + aunit0;
    const int nb2 = nq * 16;
    const int r2 = (nb2 + g) & 3;
    const uint32_t* bb2 = smw + OFF_B2 + (nb2 + g) * 64 + tq * 4;   // + n*512 + kk*16
    const int nb3 = (nq < 2) ? 32 * nq : 64 + 24 * (nq - 2);
    const int nt3 = (nq < 2) ? 4 : 3;
    const int r3 = (nb3 + g) & 3;
    const uint32_t* bb3 = smw + OFF_B3 + (nb3 + g) * 64 + tq * 4;   // + n*512 + kk*16
    // GEMM1: emb reads (rows mb+g, mb+g+8; k = 2tq, 2tq+1) and W0 units
    const float* embp = sm + OFF_EMBT + 136 * tq + mb + g;
    const uint32_t* w0u0;
    const uint32_t* w0u1;
    {
        int row0 = nb2 + g;
        int row1 = nb2 + 8 + g;
        w0u0 = smw + OFF_W0 + (row0 * 4 + ((tq + row0) & 3)) * 4;
        w0u1 = smw + OFF_W0 + (row1 * 4 + ((tq + row1) & 3)) * 4;
    }

    // per-edge identity (8 threads/edge)
    const int ge = t >> 3, gsub = t & 7;
    float* gdst = sm + OFF_SVS + ge * 84;

    // ---- loop-carried prefetch for first tile ----
    float pvx = 0.f, pvy = 0.f, pvz = 0.f;
    int psnd = 0, prec = 0;
    {
        int tile0 = blockIdx.x;
        if (tile0 < numTiles) {
            int geg0 = tile0 * TE + ge;
            if (geg0 < E) { psnd = senders[geg0]; prec = receivers[geg0]; }
            if (t < TE) {
                int e = tile0 * TE + t;
                if (e < E) { pvx = vectors[3*e+0]; pvy = vectors[3*e+1]; pvz = vectors[3*e+2]; }
            }
        }
    }

    for (int tile = blockIdx.x; tile < numTiles; tile += gridDim.x) {
        const int e0 = tile * TE;
        const int geg = e0 + ge;
        const bool gok = (geg < E);
        const int rec = prec;

        // ---- stage A: geometry + radial embedding (warps 0-1, prefetched vec) ----
        if (t < TE) {
            float vx = pvx, vy = pvy, vz = pvz;
            float r = sqrtf(vx*vx + vy*vy + vz*vz);
            float rinv = (r > 1e-12f) ? 1.0f / r : 0.0f;
            sm[OFF_US + 4*t+0] = vx*rinv; sm[OFF_US + 4*t+1] = vy*rinv;
            sm[OFF_US + 4*t+2] = vz*rinv; sm[OFF_US + 4*t+3] = 0.f;
            float env = 0.0f;
            if (r < 1.0f) {
                float x2 = r*r, x4 = x2*x2, x6 = x4*x2, x7 = x6*r, x8 = x4*x4;
                env = 1.0f - 28.0f*x6 + 48.0f*x7 - 21.0f*x8;
            }
            float pref = (r > 0.0f) ? 1.4142135623730951f * rinv * env : 0.0f;
            float s1, c1;
            sincosf(3.14159265358979323846f * r, &s1, &c1);
            float sn = s1, sp = 0.0f, c2 = 2.0f * c1;
            #pragma unroll
            for (int n = 0; n < 8; n++) {
                sm[OFF_EMBT + n*ESTR + t] = pref * sn;
                float nx = c2 * sn - sp; sp = sn; sn = nx;
            }
        }
        // gather issue (prefetched sender; latency hidden behind stage B)
        const float4* sp4 = (const float4*)(node_s + (size_t)psnd * 32);
        const float4* vp4 = (const float4*)(node_v + (size_t)psnd * 48);
        float4 gr[3];
        #pragma unroll
        for (int q = 0; q < 3; q++) {
            int f4i = gsub + 8*q;                 // 0..23, valid < 20
            float4 val = {0.f, 0.f, 0.f, 0.f};
            if (gok && f4i < 20) val = (f4i < 8) ? sp4[f4i] : vp4[f4i - 8];
            gr[q] = val;
        }
        __syncthreads();

        // ---- stage B: GEMM1 via bf16 mma (K=8 padded to 16), -> A unit k=nq ----
        {
            float e00 = embp[0], e01 = embp[ESTR];
            float e10 = embp[8], e11 = embp[ESTR + 8];
            uint32_t a0h, a0l, a1h, a1l;
            split2(e00, e01, a0h, a0l);
            split2(e10, e11, a1h, a1l);
            float acc1[2][4];
            #pragma unroll
            for (int n = 0; n < 2; n++)
                #pragma unroll
                for (int j = 0; j < 4; j++) acc1[n][j] = 0.f;
            uint4 b0 = *(const uint4*)w0u0;     // [bh0, 0, bl0, 0]
            uint4 b1 = *(const uint4*)w0u1;
            mma_bf16(acc1[0], a0h, a1h, 0u, 0u, b0.x, b0.y);
            mma_bf16(acc1[1], a0h, a1h, 0u, 0u, b1.x, b1.y);
            mma_bf16(acc1[0], a0h, a1h, 0u, 0u, b0.z, b0.w);
            mma_bf16(acc1[1], a0h, a1h, 0u, 0u, b1.z, b1.w);
            mma_bf16(acc1[0], a0l, a1l, 0u, 0u, b0.x, b0.y);
            mma_bf16(acc1[1], a0l, a1l, 0u, 0u, b1.x, b1.y);

            uint32_t h0,l0,h1,l1,h2,l2,h3,l3;
            split2(swishf(acc1[0][0]), swishf(acc1[0][1]), h0, l0);
            split2(swishf(acc1[0][2]), swishf(acc1[0][3]), h1, l1);
            split2(swishf(acc1[1][0]), swishf(acc1[1][1]), h2, l2);
            split2(swishf(acc1[1][2]), swishf(acc1[1][3]), h3, l3);
            *(uint4*)(abh + nq * 128) = make_uint4(h0, h1, h2, h3);
            *(uint4*)(abl + nq * 128) = make_uint4(l0, l1, l2, l3);
        }
        // land gather into smem; compute dots (2 per thread)
        {
            #pragma unroll
            for (int q = 0; q < 3; q++) {
                int f4i = gsub + 8*q;
                if (f4i < 20) *(float4*)(gdst + 4 * f4i) = gr[q];
            }
            __syncwarp();
            const float* usf = sm + OFF_US + 4 * ge;
            float ux = usf[0], uy = usf[1], uz = usf[2];
            #pragma unroll
            for (int q = 0; q < 2; q++) {
                int c = 2 * gsub + q;
                const float* vv = gdst + 32 + 3 * c;
                sm[OFF_DOTS + ge * 20 + c] = ux*vv[0] + uy*vv[1] + uz*vv[2];
            }
        }
        __syncthreads();

        // ---- stage C: GEMM2 via bf16 mma (3-pass split, pass-interleaved) ----
        float acc2[2][4];
        {
            #pragma unroll
            for (int n = 0; n < 2; n++)
                #pragma unroll
                for (int j = 0; j < 4; j++) acc2[n][j] = 0.f;
            #pragma unroll
            for (int k = 0; k < 4; k++) {
                const int kk = (k + r2) & 3;
                uint4 ah = *(const uint4*)(abh + k * 128);
                uint4 al = *(const uint4*)(abl + k * 128);
                uint4 b0 = *(const uint4*)(bb2 + kk * 16);
                uint4 b1 = *(const uint4*)(bb2 + 512 + kk * 16);
                mma_bf16(acc2[0], ah.x, ah.y, ah.z, ah.w, b0.x, b0.y);
                mma_bf16(acc2[1], ah.x, ah.y, ah.z, ah.w, b1.x, b1.y);
                mma_bf16(acc2[0], ah.x, ah.y, ah.z, ah.w, b0.z, b0.w);
                mma_bf16(acc2[1], ah.x, ah.y, ah.z, ah.w, b1.z, b1.w);
                mma_bf16(acc2[0], al.x, al.y, al.z, al.w, b0.x, b0.y);
                mma_bf16(acc2[1], al.x, al.y, al.z, al.w, b1.x, b1.y);
            }
        }
        __syncthreads();   // all h1 reads done before overwrite

        // ---- stage D: swish(h2), split -> packed A fragment unit k=nq ----
        {
            uint32_t h0,l0,h1,l1,h2,l2,h3,l3;
            split2(swishf(acc2[0][0]), swishf(acc2[0][1]), h0, l0);
            split2(swishf(acc2[0][2]), swishf(acc2[0][3]), h1, l1);
            split2(swishf(acc2[1][0]), swishf(acc2[1][1]), h2, l2);
            split2(swishf(acc2[1][2]), swishf(acc2[1][3]), h3, l3);
            *(uint4*)(abh + nq * 128) = make_uint4(h0, h1, h2, h3);
            *(uint4*)(abl + nq * 128) = make_uint4(l0, l1, l2, l3);
        }
        __syncthreads();

        // ---- stage E: GEMM3 via bf16 mma (3-pass split, pass-interleaved) ----
        {
            float acc3[4][4];
            #pragma unroll
            for (int n = 0; n < 4; n++)
                #pragma unroll
                for (int j = 0; j < 4; j++) acc3[n][j] = 0.f;
            #pragma unroll
            for (int k = 0; k < 4; k++) {
                const int kk = (k + r3) & 3;
                uint4 ah = *(const uint4*)(abh + k * 128);
                uint4 al = *(const uint4*)(abl + k * 128);
                uint4 b[4];
                #pragma unroll
                for (int n = 0; n < 4; n++)
                    if (n < nt3) b[n] = *(const uint4*)(bb3 + n * 512 + kk * 16);
                #pragma unroll
                for (int n = 0; n < 4; n++)
                    if (n < nt3) mma_bf16(acc3[n], ah.x, ah.y, ah.z, ah.w, b[n].x, b[n].y);
                #pragma unroll
                for (int n = 0; n < 4; n++)
                    if (n < nt3) mma_bf16(acc3[n], ah.x, ah.y, ah.z, ah.w, b[n].z, b[n].w);
                #pragma unroll
                for (int n = 0; n < 4; n++)
                    if (n < nt3) mma_bf16(acc3[n], al.x, al.y, al.z, al.w, b[n].x, b[n].y);
            }
            __syncthreads();   // A/EMBT fully read before gate store aliases them
            #pragma unroll
            for (int n = 0; n < 4; n++) {
                if (n < nt3) {
                    int col = nb3 + n*8 + 2*tq;
                    *(float2*)(sm + OFF_MIXS + (mb + g) * MIX_STRIDE + col) =
                        make_float2(acc3[n][0], acc3[n][1]);
                    *(float2*)(sm + OFF_MIXS + (mb + g + 8) * MIX_STRIDE + col) =
                        make_float2(acc3[n][2], acc3[n][3]);
                }
            }
        }
        __syncthreads();

        // ---- prefetch next tile's indices + vectors (covered by stage G drain) ----
        float nvx = 0.f, nvy = 0.f, nvz = 0.f;
        int nsnd = 0, nrec = 0;
        {
            int ntile = tile + gridDim.x;
            if (ntile < numTiles) {
                int ngeg = ntile * TE + ge;
                if (ngeg < E) { nsnd = senders[ngeg]; nrec = receivers[ngeg]; }
                if (t < TE) {
                    int ne = ntile * TE + t;
                    if (ne < E) { nvx = vectors[3*ne+0]; nvy = vectors[3*ne+1]; nvz = vectors[3*ne+2]; }
                }
            }
        }

        // ---- stage G: message formation + atomic scatter, 8 threads/edge ----
        {
            const int sub = gsub;
            const bool ok = gok;
            const float* dst = gdst;
            const float* usf = sm + OFF_US + 4 * ge;
            const float* dts = sm + OFF_DOTS + ge * 20;
            const float* mx  = sm + OFF_MIXS + ge * MIX_STRIDE;
            float* obase = out + (size_t)rec * 240;
            const float ux = usf[0], uy = usf[1], uz = usf[2];

            #pragma unroll
            for (int it = 0; it < 8; it++) {
                const int gg = 8 * it + sub;              // 0..63, valid < 60
                if (it == 7 && sub >= 4) break;
                float4 val;
                if (gg < 8) {                 // msg_s: s * gate
                    float4 s4 = *(const float4*)(dst + 4 * gg);
                    float4 m4 = *(const float4*)(mx + 4 * gg);
                    val.x = s4.x*m4.x; val.y = s4.y*m4.y; val.z = s4.z*m4.z; val.w = s4.w*m4.w;
                } else if (gg < 12) {         // msg_s: (v.u) * gate
                    float4 d4 = *(const float4*)(dts + 4 * (gg - 8));
                    float4 m4 = *(const float4*)(mx + 4 * gg);
                    val.x = d4.x*m4.x; val.y = d4.y*m4.y; val.z = d4.z*m4.z; val.w = d4.w*m4.w;
                } else {                      // msg_v flat regions
                    const int j0 = 4 * gg - 48;
                    const int ch0 = j0 / 3;
                    const int i0 = j0 - 3 * ch0;
                    const float m0 = mx[48 + ch0];
                    const float m1 = mx[48 + ch0 + 1];
                    float tmp[4];
                    if (gg < 24) {            // filtered v (ch 0..15)
                        float4 vv = *(const float4*)(dst + 32 + j0);
                        float vvq[4] = {vv.x, vv.y, vv.z, vv.w};
                        #pragma unroll
                        for (int q = 0; q < 4; q++) {
                            bool cross = (i0 + q) >= 3;
                            tmp[q] = vvq[q] * (cross ? m1 : m0);
                        }
                    } else if (gg < 48) {     // s x Y1 (ch 16..47)
                        float s0 = dst[ch0 - 16];
                        float s1 = dst[ch0 - 15];
                        #pragma unroll
                        for (int q = 0; q < 4; q++) {
                            bool cross = (i0 + q) >= 3;
                            int i = i0 + q - (cross ? 3 : 0);
                            float u = (i == 0) ? ux : ((i == 1) ? uy : uz);
                            tmp[q] = (cross ? s1 : s0) * u * (cross ? m1 : m0);
                        }
                    } else {                  // v x Y2 (ch 48..63), sqrt1.5 folded in gate
                        int jj = j0 - 144;
                        float4 vv = *(const float4*)(dst + 32 + jj);
                        float vvq[4] = {vv.x, vv.y, vv.z, vv.w};
                        float d0 = dts[ch0 - 48];
                        float d1 = dts[ch0 - 47];
                        #pragma unroll
                        for (int q = 0; q < 4; q++) {
                            bool cross = (i0 + q) >= 3;
                            int i = i0 + q - (cross ? 3 : 0);
                            float u = (i == 0) ? ux : ((i == 1) ? uy : uz);
                            float dd = cross ? d1 : d0;
                            tmp[q] = (u * dd - vvq[q] * 0.3333333333333333f) * (cross ? m1 : m0);
                        }
                    }
                    val.x = tmp[0]; val.y = tmp[1]; val.z = tmp[2]; val.w = tmp[3];
                }
                if (ok) {
                    float* addr = obase + 4 * gg;
                    asm volatile("red.global.add.v4.f32 [%0], {%1,%2,%3,%4};"
                                 :: "l"(addr), "f"(val.x), "f"(val.y), "f"(val.z), "f"(val.w)
                                 : "memory");
                }
            }
        }
        __syncthreads();   // smem reused next tile

        // carry prefetched values into next iteration
        pvx = nvx; pvy = nvy; pvz = nvz;
        psnd = nsnd; prec = nrec;
    }
}

extern "C" void kernel_launch(void* const* d_in, const int* in_sizes, int n_in,
                              void* d_out, int out_size) {
    const float* vectors   = (const float*)d_in[0];
    const float* node_s    = (const float*)d_in[1];
    const float* node_v    = (const float*)d_in[2];
    const float* W0        = (const float*)d_in[3];
    const float* W1        = (const float*)d_in[4];
    const float* W2        = (const float*)d_in[5];
    const int*   senders   = (const int*)d_in[6];
    const int*   receivers = (const int*)d_in[7];
    float*       out       = (float*)d_out;

    int E = in_sizes[6];
    int numTiles = (E + TE - 1) / TE;

    cudaFuncSetAttribute(mp_kernel, cudaFuncAttributeMaxDynamicSharedMemorySize, SMEM_BYTES);

    cudaMemsetAsync(d_out, 0, (size_t)out_size * sizeof(float), 0);

    int grid = 296;                      // persistent: 2 CTAs/SM, 32 warps/SM
    if (grid > numTiles) grid = numTiles;
    mp_kernel<<<grid, THREADS, SMEM_BYTES>>>(vectors, node_s, node_v, W0, W1, W2,
                                             senders, receivers, out, E, numTiles);
}